// round 2
// baseline (speedup 1.0000x reference)
#include <cuda_runtime.h>
#include <cstdint>

// Problem dims
#define BB 64
#define TT 128
#define CC 4096
#define HH 32
#define HSD 128
// SCALE = 32^-0.5 (fixed constant in source)
__device__ const float SCALE = 0.17677669529663687f;

// Scratch (device globals: no allocations allowed)
__device__ float g_Q[(size_t)BB*HH*TT*HSD];
__device__ float g_K[(size_t)BB*HH*TT*HSD];
__device__ float g_V[(size_t)BB*HH*TT*HSD];
__device__ float g_att[(size_t)BB*HSD*CC];

__device__ __forceinline__ uint32_t f2tf32(float f){
    uint32_t u; asm("cvt.rna.tf32.f32 %0, %1;" : "=r"(u) : "f"(f)); return u;
}
// split f into hi (tf32) + lo (tf32 of residual)
__device__ __forceinline__ void tf32_split(float f, uint32_t& hi, uint32_t& lo){
    hi = f2tf32(f);
    lo = f2tf32(f - __uint_as_float(hi));
}
__device__ __forceinline__ void mma_tf32(float* d, const uint32_t* a, uint32_t b0, uint32_t b1){
    asm volatile("mma.sync.aligned.m16n8k8.row.col.f32.tf32.tf32.f32 "
        "{%0,%1,%2,%3},{%4,%5,%6,%7},{%8,%9},{%0,%1,%2,%3};"
        : "+f"(d[0]), "+f"(d[1]), "+f"(d[2]), "+f"(d[3])
        : "r"(a[0]), "r"(a[1]), "r"(a[2]), "r"(a[3]), "r"(b0), "r"(b1));
}
// 3xTF32: acc += (ahi+alo)*(bhi+blo) dropping lo*lo
__device__ __forceinline__ void mma3(float* d, const uint32_t* ahi, const uint32_t* alo,
                                     uint32_t bh0, uint32_t bh1, uint32_t bl0, uint32_t bl1){
    mma_tf32(d, alo, bh0, bh1);
    mma_tf32(d, ahi, bl0, bl1);
    mma_tf32(d, ahi, bh0, bh1);
}
__device__ __forceinline__ void cp16(const void* smem_dst, const void* gsrc){
    uint32_t s = (uint32_t)__cvta_generic_to_shared(smem_dst);
    asm volatile("cp.async.cg.shared.global [%0], [%1], 16;" :: "r"(s), "l"(gsrc));
}
#define CP_COMMIT() asm volatile("cp.async.commit_group;")
#define CP_WAIT0()  asm volatile("cp.async.wait_group 0;")
#define CP_WAIT1()  asm volatile("cp.async.wait_group 1;")

// ---------------------------------------------------------------------------
// Tiled 3xTF32 GEMM, CTA tile 128x128, K-tile 32, 8 warps (4x2), warp 32x64
// MODE 0: QKV projection  C[(b,t),(h,s)] = x @ w{q,k,v}[h]  (B smem [k][n])
// MODE 1: output proj     C[(b,s),o]     = g_att @ wp^T + bp (B smem [n][k])
// ---------------------------------------------------------------------------
template<int MODE>
__global__ __launch_bounds__(256)
void gemm128(const float* __restrict__ A,
             const float* __restrict__ B0,
             const float* __restrict__ B1,
             const float* __restrict__ B2,
             const float* __restrict__ bias,
             float* __restrict__ Cout)
{
    constexpr int ASZ   = 128*36;                      // A smem floats per stage ([m][k], pad 4)
    constexpr int BSZ   = (MODE==0) ? 32*132 : 128*36; // B smem floats per stage
    constexpr int STAGE = ASZ + BSZ;
    constexpr int NK    = CC/32;                       // 128 k-tiles

    extern __shared__ float sm[];
    const int tid = threadIdx.x;

    // panel swizzle: 8 m-tiles x all 32 n-tiles per panel (L2 reuse)
    const int lid = blockIdx.x;
    const int pid = lid >> 8;          // / (8*32)
    const int rem = lid & 255;
    const int mt  = pid*8 + (rem & 7);
    const int nt  = rem >> 3;
    const int m0  = mt*128, n0 = nt*128;

    const float* Ab;
    const float* Bb;
    if constexpr (MODE==0){
        const int z = blockIdx.z;
        Ab = A;
        const float* w = (z==0) ? B0 : ((z==1) ? B1 : B2);
        Bb = w + (size_t)nt * ((size_t)CC*HSD);        // head nt's [C,HS] block
    } else {
        Ab = g_att;
        Bb = B0;                                       // wp [o][e]
    }

    auto loadA = [&](int st, int kt){
        float* sA = sm + st*STAGE;
        #pragma unroll
        for (int i=0;i<4;i++){
            int idx = tid + i*256;
            int r = idx>>3, c = (idx&7)*4;
            cp16(&sA[r*36+c], Ab + (size_t)(m0+r)*CC + kt*32 + c);
        }
    };
    auto loadB = [&](int st, int kt){
        float* sB = sm + st*STAGE + ASZ;
        if constexpr (MODE==0){
            #pragma unroll
            for (int i=0;i<4;i++){
                int idx = tid + i*256;
                int r = idx>>5, c = (idx&31)*4;
                cp16(&sB[r*132+c], Bb + (size_t)(kt*32+r)*HSD + c);
            }
        } else {
            #pragma unroll
            for (int i=0;i<4;i++){
                int idx = tid + i*256;
                int r = idx>>3, c = (idx&7)*4;
                cp16(&sB[r*36+c], Bb + (size_t)(n0+r)*CC + kt*32 + c);
            }
        }
    };

    const int warp = tid>>5, lane = tid&31, g = lane>>2, tg = lane&3;
    const int wm = (warp>>1)*32, wn = (warp&1)*64;

    float acc[2][8][4];
    #pragma unroll
    for (int a=0;a<2;a++)
        #pragma unroll
        for (int b=0;b<8;b++)
            #pragma unroll
            for (int c=0;c<4;c++) acc[a][b][c] = 0.f;

    loadA(0,0); loadB(0,0); CP_COMMIT();

    for (int kt=0; kt<NK; kt++){
        const int cur = kt & 1;
        if (kt+1 < NK){
            loadA(cur^1, kt+1); loadB(cur^1, kt+1); CP_COMMIT();
            CP_WAIT1();
        } else {
            CP_WAIT0();
        }
        __syncthreads();
        const float* sA = sm + cur*STAGE;
        const float* sB = sA + ASZ;
        #pragma unroll
        for (int ks=0; ks<32; ks+=8){
            uint32_t ahi[2][4], alo[2][4];
            #pragma unroll
            for (int mi=0; mi<2; mi++){
                int r = wm + mi*16 + g;
                tf32_split(sA[r*36 + ks+tg],       ahi[mi][0], alo[mi][0]);
                tf32_split(sA[(r+8)*36 + ks+tg],   ahi[mi][1], alo[mi][1]);
                tf32_split(sA[r*36 + ks+tg+4],     ahi[mi][2], alo[mi][2]);
                tf32_split(sA[(r+8)*36 + ks+tg+4], ahi[mi][3], alo[mi][3]);
            }
            #pragma unroll
            for (int ni=0; ni<8; ni++){
                int col = wn + ni*8 + g;
                float fb0, fb1;
                if constexpr (MODE==0){
                    fb0 = sB[(ks+tg)*132 + col];
                    fb1 = sB[(ks+tg+4)*132 + col];
                } else {
                    fb0 = sB[col*36 + ks+tg];
                    fb1 = sB[col*36 + ks+tg+4];
                }
                uint32_t bh0, bl0, bh1, bl1;
                tf32_split(fb0, bh0, bl0);
                tf32_split(fb1, bh1, bl1);
                mma3(acc[0][ni], ahi[0], alo[0], bh0, bh1, bl0, bl1);
                mma3(acc[1][ni], ahi[1], alo[1], bh0, bh1, bl0, bl1);
            }
        }
        __syncthreads();
    }

    if constexpr (MODE==0){
        const int z = blockIdx.z;
        float* dst = (z==0) ? g_Q : ((z==1) ? g_K : g_V);
        #pragma unroll
        for (int mi=0; mi<2; mi++){
            #pragma unroll
            for (int ni=0; ni<8; ni++){
                int mrow = m0 + wm + mi*16 + g;
                int s    = wn + ni*8 + tg*2;
                int b = mrow>>7, t = mrow&127;
                float* p = dst + ((((size_t)b*HH + nt)*TT + t)*HSD + s);
                p[0] = acc[mi][ni][0]; p[1] = acc[mi][ni][1];
                p[8*HSD] = acc[mi][ni][2]; p[8*HSD+1] = acc[mi][ni][3];
            }
        }
    } else {
        #pragma unroll
        for (int mi=0; mi<2; mi++){
            #pragma unroll
            for (int ni=0; ni<8; ni++){
                int mrow = m0 + wm + mi*16 + g;
                int ncol = n0 + wn + ni*8 + tg*2;
                float bv0 = bias[ncol], bv1 = bias[ncol+1];
                float* p = Cout + (size_t)mrow*CC + ncol;
                p[0] = acc[mi][ni][0] + bv0; p[1] = acc[mi][ni][1] + bv1;
                p[8*CC] = acc[mi][ni][2] + bv0; p[8*CC+1] = acc[mi][ni][3] + bv1;
            }
        }
    }
}

// ---------------------------------------------------------------------------
// Attention: 1 CTA per (b,h). wei = qk^T*SCALE; softmax over t (query axis!);
// out = wei @ v; store transposed into g_att[b][s][h*T + t].
// ---------------------------------------------------------------------------
__global__ __launch_bounds__(256)
void attn_kernel()
{
    extern __shared__ float sm[];
    float* sQ = sm;               // [128][132]  (later reused for V)
    float* sK = sm + 128*132;     // [128][132]  (later reused for O^T)
    float* sW = sm + 2*128*132;   // [t][u]

    const int tid = threadIdx.x;
    const int bid = blockIdx.x;
    const int h = bid & 31, b = bid >> 5;
    const float* Qb = g_Q + (size_t)(b*HH+h)*TT*HSD;
    const float* Kb = g_K + (size_t)(b*HH+h)*TT*HSD;
    const float* Vb = g_V + (size_t)(b*HH+h)*TT*HSD;

    #pragma unroll
    for (int i=0;i<16;i++){
        int idx = tid + i*256;
        int r = idx>>5, c = (idx&31)*4;
        cp16(&sQ[r*132+c], Qb + r*HSD + c);
        cp16(&sK[r*132+c], Kb + r*HSD + c);
    }
    CP_COMMIT(); CP_WAIT0();
    __syncthreads();

    const int warp = tid>>5, lane = tid&31, g = lane>>2, tg = lane&3;
    const int wm = (warp>>1)*32, wn = (warp&1)*64;

    // wei[t][u] = sum_s q[t,s] k[u,s]
    {
        float acc[2][8][4];
        #pragma unroll
        for (int a=0;a<2;a++)
            #pragma unroll
            for (int c2=0;c2<8;c2++)
                #pragma unroll
                for (int d2=0;d2<4;d2++) acc[a][c2][d2]=0.f;
        #pragma unroll
        for (int ks=0; ks<128; ks+=8){
            uint32_t ahi[2][4], alo[2][4];
            #pragma unroll
            for (int mi=0; mi<2; mi++){
                int r = wm + mi*16 + g;
                tf32_split(sQ[r*132 + ks+tg],       ahi[mi][0], alo[mi][0]);
                tf32_split(sQ[(r+8)*132 + ks+tg],   ahi[mi][1], alo[mi][1]);
                tf32_split(sQ[r*132 + ks+tg+4],     ahi[mi][2], alo[mi][2]);
                tf32_split(sQ[(r+8)*132 + ks+tg+4], ahi[mi][3], alo[mi][3]);
            }
            #pragma unroll
            for (int ni=0; ni<8; ni++){
                int col = wn + ni*8 + g;
                uint32_t bh0, bl0, bh1, bl1;
                tf32_split(sK[col*132 + ks+tg],   bh0, bl0);
                tf32_split(sK[col*132 + ks+tg+4], bh1, bl1);
                mma3(acc[0][ni], ahi[0], alo[0], bh0, bh1, bl0, bl1);
                mma3(acc[1][ni], ahi[1], alo[1], bh0, bh1, bl0, bl1);
            }
        }
        #pragma unroll
        for (int mi=0; mi<2; mi++){
            #pragma unroll
            for (int ni=0; ni<8; ni++){
                int r = wm + mi*16 + g;
                int c = wn + ni*8 + tg*2;
                sW[r*132+c]       = acc[mi][ni][0]*SCALE;
                sW[r*132+c+1]     = acc[mi][ni][1]*SCALE;
                sW[(r+8)*132+c]   = acc[mi][ni][2]*SCALE;
                sW[(r+8)*132+c+1] = acc[mi][ni][3]*SCALE;
            }
        }
    }
    __syncthreads();

    // softmax over t per column u (threads 0..127); threads 128..255 load V
    if (tid < 128){
        const int u = tid;
        float mx = -1e30f;
        for (int t=0;t<128;t++) mx = fmaxf(mx, sW[t*132+u]);
        float ssum = 0.f;
        for (int t=0;t<128;t++){ float e = __expf(sW[t*132+u]-mx); sW[t*132+u]=e; ssum+=e; }
        float inv = 1.f/ssum;
        for (int t=0;t<128;t++) sW[t*132+u] *= inv;
    } else {
        const int lt = tid - 128;
        #pragma unroll
        for (int i=0;i<32;i++){
            int idx = lt + i*128;
            int r = idx>>5, c = (idx&31)*4;
            cp16(&sQ[r*132+c], Vb + r*HSD + c);   // V into sQ region
        }
        CP_COMMIT(); CP_WAIT0();
    }
    __syncthreads();

    // out[t][s] = sum_u wei[t,u] v[u,s]
    {
        float acc[2][8][4];
        #pragma unroll
        for (int a=0;a<2;a++)
            #pragma unroll
            for (int c2=0;c2<8;c2++)
                #pragma unroll
                for (int d2=0;d2<4;d2++) acc[a][c2][d2]=0.f;
        #pragma unroll
        for (int ks=0; ks<128; ks+=8){
            uint32_t ahi[2][4], alo[2][4];
            #pragma unroll
            for (int mi=0; mi<2; mi++){
                int r = wm + mi*16 + g;
                tf32_split(sW[r*132 + ks+tg],       ahi[mi][0], alo[mi][0]);
                tf32_split(sW[(r+8)*132 + ks+tg],   ahi[mi][1], alo[mi][1]);
                tf32_split(sW[r*132 + ks+tg+4],     ahi[mi][2], alo[mi][2]);
                tf32_split(sW[(r+8)*132 + ks+tg+4], ahi[mi][3], alo[mi][3]);
            }
            #pragma unroll
            for (int ni=0; ni<8; ni++){
                int col = wn + ni*8 + g;
                uint32_t bh0, bl0, bh1, bl1;
                tf32_split(sQ[(ks+tg)*132 + col],   bh0, bl0);
                tf32_split(sQ[(ks+tg+4)*132 + col], bh1, bl1);
                mma3(acc[0][ni], ahi[0], alo[0], bh0, bh1, bl0, bl1);
                mma3(acc[1][ni], ahi[1], alo[1], bh0, bh1, bl0, bl1);
            }
        }
        // store transposed: sO[s][t] into sK region
        #pragma unroll
        for (int mi=0; mi<2; mi++){
            #pragma unroll
            for (int ni=0; ni<8; ni++){
                int r = wm + mi*16 + g;
                int c = wn + ni*8 + tg*2;
                sK[c*132 + r]       = acc[mi][ni][0];
                sK[(c+1)*132 + r]   = acc[mi][ni][1];
                sK[c*132 + r+8]     = acc[mi][ni][2];
                sK[(c+1)*132 + r+8] = acc[mi][ni][3];
            }
        }
    }
    __syncthreads();

    // g_att[b][s][h*T + t]
    float* ob = g_att + (size_t)b*(HSD*CC) + (size_t)h*TT;
    #pragma unroll
    for (int i=0;i<16;i++){
        int idx = tid + i*256;
        int s = idx>>5, t4 = (idx&31)*4;
        float4 v = *(const float4*)&sK[s*132 + t4];
        *(float4*)&ob[(size_t)s*CC + t4] = v;
    }
}

extern "C" void kernel_launch(void* const* d_in, const int* in_sizes, int n_in,
                              void* d_out, int out_size)
{
    const float* x  = (const float*)d_in[0];
    const float* wq = (const float*)d_in[1];
    const float* wk = (const float*)d_in[2];
    const float* wv = (const float*)d_in[3];
    const float* wp = (const float*)d_in[4];
    const float* bp = (const float*)d_in[5];
    float* out = (float*)d_out;

    const int smem0 = (128*36 + 32*132)*2*4;   // 70656 B
    const int smem1 = (128*36 + 128*36)*2*4;   // 73728 B
    const int smemA = 3*128*132*4;             // 202752 B
    cudaFuncSetAttribute(gemm128<0>, cudaFuncAttributeMaxDynamicSharedMemorySize, smem0);
    cudaFuncSetAttribute(gemm128<1>, cudaFuncAttributeMaxDynamicSharedMemorySize, smem1);
    cudaFuncSetAttribute(attn_kernel, cudaFuncAttributeMaxDynamicSharedMemorySize, smemA);

    // Pass 1: Q,K,V projections (z selects which weight)
    gemm128<0><<<dim3(2048,1,3), 256, smem0>>>(x, wq, wk, wv, nullptr, nullptr);
    // Pass 2: per-(b,h) attention with softmax over query axis
    attn_kernel<<<2048, 256, smemA>>>();
    // Pass 3: output projection + bias
    gemm128<1><<<dim3(2048,1,1), 256, smem1>>>(nullptr, wp, nullptr, nullptr, bp, out);
}